// round 10
// baseline (speedup 1.0000x reference)
#include <cuda_runtime.h>
#include <cuda_fp16.h>
#include <cstdint>

#define NB 2
#define SEQ 2048
#define EMB 1024
#define NHEADS 16
#define NROWS (NB * SEQ)

// Scratch (__device__ globals per allocation rules)
__device__ __half g_wh[EMB * EMB];          // folded Wv/Wo fp16: [k'][n]
__device__ __half g_vh[NROWS * EMB];        // value as fp16
__device__ __half g_vch[NROWS * EMB];       // Vc = value @ Wcomb, fp16
__device__ __half g_afh[(long)NROWS * SEQ]; // binary mask fp16: 1.0 where mask==0
__device__ float  g_invcnt[NROWS];          // 1 / (# zeros in row), fp32

// ---------------------------------------------------------------------------
__device__ __forceinline__ void mma_f16(float c[4],
                                        uint32_t a0, uint32_t a1, uint32_t a2, uint32_t a3,
                                        uint32_t b0, uint32_t b1) {
    asm volatile(
        "mma.sync.aligned.m16n8k16.row.col.f32.f16.f16.f32 "
        "{%0,%1,%2,%3}, {%4,%5,%6,%7}, {%8,%9}, {%0,%1,%2,%3};"
        : "+f"(c[0]), "+f"(c[1]), "+f"(c[2]), "+f"(c[3])
        : "r"(a0), "r"(a1), "r"(a2), "r"(a3), "r"(b0), "r"(b1));
}

__device__ __forceinline__ void ldsm_x4(uint32_t& r0, uint32_t& r1,
                                        uint32_t& r2, uint32_t& r3, uint32_t addr) {
    asm volatile("ldmatrix.sync.aligned.m8n8.x4.shared.b16 {%0,%1,%2,%3}, [%4];"
                 : "=r"(r0), "=r"(r1), "=r"(r2), "=r"(r3) : "r"(addr));
}
__device__ __forceinline__ void ldsm_x4_t(uint32_t& r0, uint32_t& r1,
                                          uint32_t& r2, uint32_t& r3, uint32_t addr) {
    asm volatile("ldmatrix.sync.aligned.m8n8.x4.trans.shared.b16 {%0,%1,%2,%3}, [%4];"
                 : "=r"(r0), "=r"(r1), "=r"(r2), "=r"(r3) : "r"(addr));
}

__device__ __forceinline__ void cp16(uint32_t s, const void* g) {
    asm volatile("cp.async.cg.shared.global [%0], [%1], 16;" :: "r"(s), "l"(g));
}
__device__ __forceinline__ void cp_commit() { asm volatile("cp.async.commit_group;"); }
__device__ __forceinline__ void cp_wait0()  { asm volatile("cp.async.wait_group 0;"); }
__device__ __forceinline__ void cp_wait1()  { asm volatile("cp.async.wait_group 1;"); }

// ---------------------------------------------------------------------------
// Kernel 1: Wcomb[h*64+d'][n] = sum_d Wv[d][d'] * Wo[n][h*64+d]  -> fp16
// ---------------------------------------------------------------------------
__global__ __launch_bounds__(256) void wcomb_kernel(
    const float* __restrict__ Wv, const float* __restrict__ Wo)
{
    __shared__ float sWv[64][68];
    __shared__ float sWoT[64][68];

    const int h = blockIdx.x;
    const int n0 = blockIdx.y * 64;
    const int tid = threadIdx.x;

    for (int i = tid; i < 4096; i += 256) {
        int d = i >> 6, r = i & 63;
        sWv[d][r] = Wv[i];
    }
    for (int i = tid; i < 4096; i += 256) {
        int c = i >> 6, d = i & 63;
        sWoT[d][c] = Wo[(long)(n0 + c) * EMB + h * 64 + d];
    }
    __syncthreads();

    const int tr = (tid >> 4) * 4, tc = (tid & 15) * 4;
    float acc[4][4];
#pragma unroll
    for (int i = 0; i < 4; i++)
#pragma unroll
        for (int j = 0; j < 4; j++) acc[i][j] = 0.f;

#pragma unroll
    for (int d = 0; d < 64; d++) {
        float4 av = *(const float4*)&sWv[d][tr];
        float4 bv = *(const float4*)&sWoT[d][tc];
        float a[4] = {av.x, av.y, av.z, av.w};
        float b[4] = {bv.x, bv.y, bv.z, bv.w};
#pragma unroll
        for (int i = 0; i < 4; i++)
#pragma unroll
            for (int j = 0; j < 4; j++) acc[i][j] += a[i] * b[j];
    }

#pragma unroll
    for (int i = 0; i < 4; i++) {
        __half2 h0 = __floats2half2_rn(acc[i][0], acc[i][1]);
        __half2 h1 = __floats2half2_rn(acc[i][2], acc[i][3]);
        uint2 w = make_uint2(*(uint32_t*)&h0, *(uint32_t*)&h1);
        *(uint2*)(g_wh + (long)(h * 64 + tr + i) * EMB + n0 + tc) = w;
    }
}

// ---------------------------------------------------------------------------
// Kernel 2: value fp32 -> fp16
// ---------------------------------------------------------------------------
__global__ __launch_bounds__(256) void cvtv_kernel(const float* __restrict__ V)
{
    long i = (long)blockIdx.x * 256 + threadIdx.x;
    float4 v = ((const float4*)V)[i];
    __half2 h0 = __floats2half2_rn(v.x, v.y);
    __half2 h1 = __floats2half2_rn(v.z, v.w);
    ((uint2*)g_vh)[i] = make_uint2(*(uint32_t*)&h0, *(uint32_t*)&h1);
}

// ---------------------------------------------------------------------------
// Kernel 3: mask row -> binary fp16 (1.0 where mask==0) + fp32 1/count
// ---------------------------------------------------------------------------
__global__ __launch_bounds__(256) void maskf_kernel(const int* __restrict__ mask)
{
    const int tid = threadIdx.x;
    const long base = (long)blockIdx.x * SEQ;
    const int4* mp = (const int4*)(mask + base);

    int4 a = mp[tid];
    int4 b = mp[tid + 256];
    int c = (a.x == 0) + (a.y == 0) + (a.z == 0) + (a.w == 0)
          + (b.x == 0) + (b.y == 0) + (b.z == 0) + (b.w == 0);

#pragma unroll
    for (int off = 16; off > 0; off >>= 1)
        c += __shfl_down_sync(0xffffffffu, c, off);

    __shared__ int ws[8];
    if ((tid & 31) == 0) ws[tid >> 5] = c;
    __syncthreads();
    if (tid == 0) {
        int t = 0;
#pragma unroll
        for (int i = 0; i < 8; i++) t += ws[i];
        g_invcnt[blockIdx.x] = 1.0f / (float)t;
    }

    const uint32_t ONE = 0x3C00u;
    uint2 w0, w1;
    w0.x = ((a.x == 0) ? ONE : 0u) | (((a.y == 0) ? ONE : 0u) << 16);
    w0.y = ((a.z == 0) ? ONE : 0u) | (((a.w == 0) ? ONE : 0u) << 16);
    w1.x = ((b.x == 0) ? ONE : 0u) | (((b.y == 0) ? ONE : 0u) << 16);
    w1.y = ((b.z == 0) ? ONE : 0u) | (((b.w == 0) ? ONE : 0u) << 16);
    *(uint2*)(g_afh + base + tid * 4) = w0;
    *(uint2*)(g_afh + base + 1024 + tid * 4) = w1;
}

// ---------------------------------------------------------------------------
// fp16 GEMM: block 128x128, BK=64, 8 warps (2m x 4n), warp tile 64x32,
// m16n8k16 MMA, ldmatrix A (x4) + B (x4.trans), 3-stage cp.async (load after
// sync, 2-iter lookahead), one __syncthreads per iter, 2 CTAs/SM.
// A smem: rows padded to 72 halves (144B) -> conflict-free ldsm (72/8 odd).
// B smem: [k][128] halves, 16B-chunk XOR swizzle (cc ^ (k&7)).
// ---------------------------------------------------------------------------
#define BM 128
#define BN 128
#define BK 64
#define NSTG 3
#define A_BYTES (BM * 72 * 2)          // 18432
#define B_BYTES (BK * BN * 2)          // 16384
#define GSMEM_BYTES (NSTG * (A_BYTES + B_BYTES))   // 104448

__device__ __forceinline__ void gemm_load_h(uint32_t sA, uint32_t sB,
                                            const __half* Ab, long astride,
                                            const __half* Bb, int tid, int k0, int st)
{
#pragma unroll
    for (int u = 0; u < 4; u++) {
        int ch = tid + u * 256;            // 1024 chunks: 128 rows x 8
        int r = ch >> 3, cc = ch & 7;
        cp16(sA + (uint32_t)(st * A_BYTES) + (uint32_t)(r * 72 + cc * 8) * 2,
             Ab + (long)r * astride + k0 + cc * 8);
    }
#pragma unroll
    for (int u = 0; u < 4; u++) {
        int ch = tid + u * 256;            // 1024 chunks: 64 rows x 16
        int r = ch >> 4, cc = ch & 15;
        cp16(sB + (uint32_t)(st * B_BYTES) + (uint32_t)(r * 128 + ((cc ^ (r & 7)) * 8)) * 2,
             Bb + (long)(k0 + r) * EMB + cc * 8);
    }
    cp_commit();
}

__device__ __forceinline__ void gemm_core_h(const __half* Ab, long astride,
                                            const __half* Bb,
                                            float acc[4][4][4], int nIter)
{
    extern __shared__ char smh[];
    uint32_t sA = (uint32_t)__cvta_generic_to_shared(smh);
    uint32_t sB = sA + NSTG * A_BYTES;

    const int tid = threadIdx.x;
    const int wid = tid >> 5, lane = tid & 31;
    const int wm = (wid >> 2) * 64;
    const int wn = (wid & 3) * 32;

    const int lrow = lane & 15;
    const int lk8 = (lane & 16) >> 1;      // 0 or 8 (A k-offset)
    const int bhi = (lane >> 4) & 1;       // B: +1 chunk for n+8 matrices

    uint32_t aoff[4];
#pragma unroll
    for (int mt = 0; mt < 4; mt++)
        aoff[mt] = (uint32_t)((wm + mt * 16 + lrow) * 72 + lk8) * 2;

    gemm_load_h(sA, sB, Ab, astride, Bb, tid, 0, 0);
    gemm_load_h(sA, sB, Ab, astride, Bb, tid, BK, 1);

    for (int i = 0; i < nIter; i++) {
        if (i < nIter - 1) cp_wait1(); else cp_wait0();
        __syncthreads();
        // slot (i+2)%NSTG was computed at iter i-1 -> free after this barrier
        if (i + 2 < nIter)
            gemm_load_h(sA, sB, Ab, astride, Bb, tid, (i + 2) * BK, (i + 2) % NSTG);

        const int st = i % NSTG;
        const uint32_t aS = sA + (uint32_t)(st * A_BYTES);
        const uint32_t bS = sB + (uint32_t)(st * B_BYTES);

#pragma unroll
        for (int ks = 0; ks < 4; ks++) {
            const int kb = ks * 16;
            uint32_t a[4][4], br[2][4];
#pragma unroll
            for (int mt = 0; mt < 4; mt++)
                ldsm_x4(a[mt][0], a[mt][1], a[mt][2], a[mt][3],
                        aS + aoff[mt] + kb * 2);
#pragma unroll
            for (int nt2 = 0; nt2 < 2; nt2++) {
                int krow = kb + lrow;
                int nc = ((wn + nt2 * 16) >> 3) + bhi;
                int cs = nc ^ (krow & 7);
                ldsm_x4_t(br[nt2][0], br[nt2][1], br[nt2][2], br[nt2][3],
                          bS + (uint32_t)(krow * 128 + cs * 8) * 2);
            }
#pragma unroll
            for (int mt = 0; mt < 4; mt++)
#pragma unroll
                for (int nt = 0; nt < 4; nt++) {
                    int nt2 = nt >> 1, pr = (nt & 1) * 2;
                    mma_f16(acc[mt][nt], a[mt][0], a[mt][1], a[mt][2], a[mt][3],
                            br[nt2][pr], br[nt2][pr + 1]);
                }
        }
    }
}

// Kernel 4: Vc = g_vh @ g_wh  (fp16 in, fp32 acc, fp16 out)
__global__ __launch_bounds__(256, 2) void vc_gemm_kernel()
{
    const int tid = threadIdx.x;
    const int wid = tid >> 5, lane = tid & 31;
    const int gid = lane >> 2, tig = lane & 3;
    const int wm = (wid >> 2) * 64;
    const int wn = (wid & 3) * 32;

    const int e0 = blockIdx.x * BN;
    const int row0 = blockIdx.y * BM;

    float acc[4][4][4];
#pragma unroll
    for (int a = 0; a < 4; a++)
#pragma unroll
        for (int b = 0; b < 4; b++)
#pragma unroll
            for (int c = 0; c < 4; c++) acc[a][b][c] = 0.f;

    gemm_core_h(g_vh + (long)row0 * EMB, EMB, g_wh + e0, acc, EMB / BK);

#pragma unroll
    for (int mt = 0; mt < 4; mt++) {
        int r0a = row0 + wm + mt * 16 + gid;
#pragma unroll
        for (int nt = 0; nt < 4; nt++) {
            int col = e0 + wn + nt * 8 + 2 * tig;
            __half2 h0 = __floats2half2_rn(acc[mt][nt][0], acc[mt][nt][1]);
            __half2 h1 = __floats2half2_rn(acc[mt][nt][2], acc[mt][nt][3]);
            *(__half2*)(g_vch + (long)r0a * EMB + col) = h0;
            *(__half2*)(g_vch + (long)(r0a + 8) * EMB + col) = h1;
        }
    }
}

// Kernel 5: out = diag(invcnt) * (g_afh @ g_vch) + bo
__global__ __launch_bounds__(256, 2) void masked_gemm_kernel(
    const float* __restrict__ bo, float* __restrict__ Y)
{
    const int tid = threadIdx.x;
    const int wid = tid >> 5, lane = tid & 31;
    const int gid = lane >> 2, tig = lane & 3;
    const int wm = (wid >> 2) * 64;
    const int wn = (wid & 3) * 32;

    const int e0 = blockIdx.x * BN;
    const int row0 = blockIdx.y * BM;
    const int n = row0 / SEQ;

    float acc[4][4][4];
#pragma unroll
    for (int a = 0; a < 4; a++)
#pragma unroll
        for (int b = 0; b < 4; b++)
#pragma unroll
            for (int c = 0; c < 4; c++) acc[a][b][c] = 0.f;

    gemm_core_h(g_afh + (long)row0 * SEQ, SEQ,
                g_vch + (long)n * SEQ * EMB + e0, acc, SEQ / BK);

#pragma unroll
    for (int mt = 0; mt < 4; mt++) {
        int r0a = row0 + wm + mt * 16 + gid;
        float s0 = g_invcnt[r0a];
        float s1 = g_invcnt[r0a + 8];
#pragma unroll
        for (int nt = 0; nt < 4; nt++) {
            int col = e0 + wn + nt * 8 + 2 * tig;
            float b0v = bo[col], b1v = bo[col + 1];
            float2 v0 = make_float2(acc[mt][nt][0] * s0 + b0v, acc[mt][nt][1] * s0 + b1v);
            float2 v1 = make_float2(acc[mt][nt][2] * s1 + b0v, acc[mt][nt][3] * s1 + b1v);
            *(float2*)(Y + (long)r0a * EMB + col) = v0;
            *(float2*)(Y + (long)(r0a + 8) * EMB + col) = v1;
        }
    }
}

// ---------------------------------------------------------------------------
extern "C" void kernel_launch(void* const* d_in, const int* in_sizes, int n_in,
                              void* d_out, int out_size)
{
    const float* value = (const float*)d_in[0];
    // key/query/Wk/Wq unused: masked_fill(+1e20) before softmax forces all
    // unmasked scores to underflow; output is the masked average of projected V.
    const int*   mask  = (const int*)d_in[3];
    const float* Wv    = (const float*)d_in[4];
    const float* Wo    = (const float*)d_in[7];
    const float* bo    = (const float*)d_in[8];
    float* out = (float*)d_out;

    cudaFuncSetAttribute(vc_gemm_kernel,
                         cudaFuncAttributeMaxDynamicSharedMemorySize, GSMEM_BYTES);
    cudaFuncSetAttribute(masked_gemm_kernel,
                         cudaFuncAttributeMaxDynamicSharedMemorySize, GSMEM_BYTES);

    {
        dim3 grid(NHEADS, EMB / 64);
        wcomb_kernel<<<grid, 256>>>(Wv, Wo);
    }
    cvtv_kernel<<<NROWS * EMB / 4 / 256, 256>>>(value);
    maskf_kernel<<<NROWS, 256>>>(mask);
    {
        dim3 grid(EMB / BN, NROWS / BM);
        vc_gemm_kernel<<<grid, 256, GSMEM_BYTES>>>();
    }
    {
        dim3 grid(EMB / BN, NROWS / BM);
        masked_gemm_kernel<<<grid, 256, GSMEM_BYTES>>>(bo, out);
    }
}

// round 11
// speedup vs baseline: 1.0212x; 1.0212x over previous
#include <cuda_runtime.h>
#include <cuda_fp16.h>
#include <cstdint>

#define NB 2
#define SEQ 2048
#define EMB 1024
#define NHEADS 16
#define NROWS (NB * SEQ)

// Scratch (__device__ globals per allocation rules)
__device__ __half g_wh[EMB * EMB];          // folded Wv/Wo fp16: [k'][n]
__device__ __half g_vh[NROWS * EMB];        // value as fp16
__device__ __half g_vch[NROWS * EMB];       // Vc = value @ Wcomb, fp16
__device__ __half g_afh[(long)NROWS * SEQ]; // binary mask fp16: 1.0 where mask==0
__device__ float  g_invcnt[NROWS];          // 1 / (# zeros in row), fp32

// ---------------------------------------------------------------------------
__device__ __forceinline__ void mma_f16(float c[4],
                                        uint32_t a0, uint32_t a1, uint32_t a2, uint32_t a3,
                                        uint32_t b0, uint32_t b1) {
    asm volatile(
        "mma.sync.aligned.m16n8k16.row.col.f32.f16.f16.f32 "
        "{%0,%1,%2,%3}, {%4,%5,%6,%7}, {%8,%9}, {%0,%1,%2,%3};"
        : "+f"(c[0]), "+f"(c[1]), "+f"(c[2]), "+f"(c[3])
        : "r"(a0), "r"(a1), "r"(a2), "r"(a3), "r"(b0), "r"(b1));
}

__device__ __forceinline__ void ldsm_x4(uint32_t& r0, uint32_t& r1,
                                        uint32_t& r2, uint32_t& r3, uint32_t addr) {
    asm volatile("ldmatrix.sync.aligned.m8n8.x4.shared.b16 {%0,%1,%2,%3}, [%4];"
                 : "=r"(r0), "=r"(r1), "=r"(r2), "=r"(r3) : "r"(addr));
}
__device__ __forceinline__ void ldsm_x4_t(uint32_t& r0, uint32_t& r1,
                                          uint32_t& r2, uint32_t& r3, uint32_t addr) {
    asm volatile("ldmatrix.sync.aligned.m8n8.x4.trans.shared.b16 {%0,%1,%2,%3}, [%4];"
                 : "=r"(r0), "=r"(r1), "=r"(r2), "=r"(r3) : "r"(addr));
}

__device__ __forceinline__ void cp16(uint32_t s, const void* g) {
    asm volatile("cp.async.cg.shared.global [%0], [%1], 16;" :: "r"(s), "l"(g));
}
__device__ __forceinline__ void cp_commit() { asm volatile("cp.async.commit_group;"); }
__device__ __forceinline__ void cp_wait0()  { asm volatile("cp.async.wait_group 0;"); }
__device__ __forceinline__ void cp_wait1()  { asm volatile("cp.async.wait_group 1;"); }
__device__ __forceinline__ void cp_wait2()  { asm volatile("cp.async.wait_group 2;"); }

// ---------------------------------------------------------------------------
// Fused prep kernel, grid partition:
//  blocks [0,256):        wcomb -> g_wh
//  blocks [256,2304):     value fp32 -> fp16 (2 float4 per thread)
//  blocks [2304,6400):    mask -> binary fp16 + 1/count
// ---------------------------------------------------------------------------
#define PREP_GRID 6400

__global__ __launch_bounds__(256) void prep_kernel(
    const float* __restrict__ value, const int* __restrict__ mask,
    const float* __restrict__ Wv, const float* __restrict__ Wo)
{
    const int b = blockIdx.x;
    const int tid = threadIdx.x;

    if (b < 256) {
        // ---- wcomb: Wcomb[h*64+d'][n] = sum_d Wv[d][d'] * Wo[n][h*64+d]
        __shared__ float sWv[64][68];
        __shared__ float sWoT[64][68];
        const int h = b >> 4;
        const int n0 = (b & 15) * 64;

        for (int i = tid; i < 4096; i += 256) {
            int d = i >> 6, r = i & 63;
            sWv[d][r] = Wv[i];
        }
        for (int i = tid; i < 4096; i += 256) {
            int c = i >> 6, d = i & 63;
            sWoT[d][c] = Wo[(long)(n0 + c) * EMB + h * 64 + d];
        }
        __syncthreads();

        const int tr = (tid >> 4) * 4, tc = (tid & 15) * 4;
        float acc[4][4];
#pragma unroll
        for (int i = 0; i < 4; i++)
#pragma unroll
            for (int j = 0; j < 4; j++) acc[i][j] = 0.f;
#pragma unroll
        for (int d = 0; d < 64; d++) {
            float4 av = *(const float4*)&sWv[d][tr];
            float4 bv = *(const float4*)&sWoT[d][tc];
            float a[4] = {av.x, av.y, av.z, av.w};
            float bb[4] = {bv.x, bv.y, bv.z, bv.w};
#pragma unroll
            for (int i = 0; i < 4; i++)
#pragma unroll
                for (int j = 0; j < 4; j++) acc[i][j] += a[i] * bb[j];
        }
#pragma unroll
        for (int i = 0; i < 4; i++) {
            __half2 h0 = __floats2half2_rn(acc[i][0], acc[i][1]);
            __half2 h1 = __floats2half2_rn(acc[i][2], acc[i][3]);
            uint2 w = make_uint2(*(uint32_t*)&h0, *(uint32_t*)&h1);
            *(uint2*)(g_wh + (long)(h * 64 + tr + i) * EMB + n0 + tc) = w;
        }
    } else if (b < 2304) {
        // ---- cvtv: 2048 blocks, 2 float4 per thread (1M float4 total)
        long i0 = (long)(b - 256) * 512 + tid;
#pragma unroll
        for (int u = 0; u < 2; u++) {
            long i = i0 + u * 256;
            float4 v = ((const float4*)value)[i];
            __half2 h0 = __floats2half2_rn(v.x, v.y);
            __half2 h1 = __floats2half2_rn(v.z, v.w);
            ((uint2*)g_vh)[i] = make_uint2(*(uint32_t*)&h0, *(uint32_t*)&h1);
        }
    } else {
        // ---- maskf: one mask row per block
        const int row = b - 2304;
        const long base = (long)row * SEQ;
        const int4* mp = (const int4*)(mask + base);

        int4 a = mp[tid];
        int4 bb = mp[tid + 256];
        int c = (a.x == 0) + (a.y == 0) + (a.z == 0) + (a.w == 0)
              + (bb.x == 0) + (bb.y == 0) + (bb.z == 0) + (bb.w == 0);
#pragma unroll
        for (int off = 16; off > 0; off >>= 1)
            c += __shfl_down_sync(0xffffffffu, c, off);

        __shared__ int ws[8];
        if ((tid & 31) == 0) ws[tid >> 5] = c;
        __syncthreads();
        if (tid == 0) {
            int t = 0;
#pragma unroll
            for (int i = 0; i < 8; i++) t += ws[i];
            g_invcnt[row] = 1.0f / (float)t;
        }

        const uint32_t ONE = 0x3C00u;
        uint2 w0, w1;
        w0.x = ((a.x == 0) ? ONE : 0u) | (((a.y == 0) ? ONE : 0u) << 16);
        w0.y = ((a.z == 0) ? ONE : 0u) | (((a.w == 0) ? ONE : 0u) << 16);
        w1.x = ((bb.x == 0) ? ONE : 0u) | (((bb.y == 0) ? ONE : 0u) << 16);
        w1.y = ((bb.z == 0) ? ONE : 0u) | (((bb.w == 0) ? ONE : 0u) << 16);
        *(uint2*)(g_afh + base + tid * 4) = w0;
        *(uint2*)(g_afh + base + 1024 + tid * 4) = w1;
    }
}

// ---------------------------------------------------------------------------
// fp16 GEMM core, templated on BN and thread count.
// Block M=128, BK=32, warp tile 64x32, m16n8k16, ldmatrix A(x4)/B(x4.trans),
// NSTG=4 cp.async pipeline (3-deep lookahead), 1 sync/iter.
// A smem: 128 rows x 40 halves (pad) -> conflict-free ldsm.
// B smem: [32][BN] halves, 16B-chunk swizzle cc ^ (r&7).
// ---------------------------------------------------------------------------
#define BM 128
#define BK 32
#define NSTG 4
#define A_BYTES (BM * 40 * 2)                       // 10240

template <int BN_, int NT_>
__device__ __forceinline__ void gemm_core_h(const __half* Ab, long astride,
                                            const __half* Bb,
                                            float acc[4][4][4], int nIter)
{
    constexpr int B_BYTES_ = BK * BN_ * 2;
    extern __shared__ char smh[];
    uint32_t sA = (uint32_t)__cvta_generic_to_shared(smh);
    uint32_t sB = sA + NSTG * A_BYTES;

    const int tid = threadIdx.x;
    const int wid = tid >> 5, lane = tid & 31;
    constexpr int NW_N = BN_ / 32;                  // n-warps
    const int wm = (wid / NW_N) * 64;
    const int wn = (wid % NW_N) * 32;

    const int lrow = lane & 15;
    const int lk8 = (lane & 16) >> 1;
    const int bhi = (lane >> 4) & 1;

    uint32_t aoff[4];
#pragma unroll
    for (int mt = 0; mt < 4; mt++)
        aoff[mt] = (uint32_t)((wm + mt * 16 + lrow) * 40 + lk8) * 2;

    // loader lambda-equivalent
    auto load_tiles = [&](int k0, int st) {
#pragma unroll
        for (int ch = tid; ch < 512; ch += NT_) {   // A: 128 rows x 4 chunks
            int r = ch >> 2, cc = ch & 3;
            cp16(sA + (uint32_t)(st * A_BYTES) + (uint32_t)(r * 40 + cc * 8) * 2,
                 Ab + (long)r * astride + k0 + cc * 8);
        }
#pragma unroll
        for (int ch = tid; ch < 4 * BN_; ch += NT_) { // B: 32 rows x BN_/8 chunks
            int r = ch / (BN_ / 8), cc = ch % (BN_ / 8);
            cp16(sB + (uint32_t)(st * B_BYTES_) +
                     (uint32_t)(r * BN_ + ((cc ^ (r & 7)) * 8)) * 2,
                 Bb + (long)(k0 + r) * EMB + cc * 8);
        }
        cp_commit();
    };

    load_tiles(0, 0);
    load_tiles(BK, 1);
    load_tiles(2 * BK, 2);

    for (int i = 0; i < nIter; i++) {
        const int rem = nIter - 1 - i;
        if (rem >= 2) cp_wait2();
        else if (rem == 1) cp_wait1();
        else cp_wait0();
        __syncthreads();
        if (i + 3 < nIter) load_tiles((i + 3) * BK, (i + 3) % NSTG);

        const int st = i % NSTG;
        const uint32_t aS = sA + (uint32_t)(st * A_BYTES);
        const uint32_t bS = sB + (uint32_t)(st * B_BYTES_);

#pragma unroll
        for (int ks = 0; ks < 2; ks++) {
            const int kb = ks * 16;
            uint32_t a[4][4], br[2][4];
#pragma unroll
            for (int mt = 0; mt < 4; mt++)
                ldsm_x4(a[mt][0], a[mt][1], a[mt][2], a[mt][3],
                        aS + aoff[mt] + kb * 2);
#pragma unroll
            for (int nt2 = 0; nt2 < 2; nt2++) {
                int krow = kb + lrow;
                int nc = ((wn + nt2 * 16) >> 3) + bhi;
                int cs = nc ^ (krow & 7);
                ldsm_x4_t(br[nt2][0], br[nt2][1], br[nt2][2], br[nt2][3],
                          bS + (uint32_t)(krow * BN_ + cs * 8) * 2);
            }
#pragma unroll
            for (int mt = 0; mt < 4; mt++)
#pragma unroll
                for (int nt = 0; nt < 4; nt++) {
                    int nt2 = nt >> 1, pr = (nt & 1) * 2;
                    mma_f16(acc[mt][nt], a[mt][0], a[mt][1], a[mt][2], a[mt][3],
                            br[nt2][pr], br[nt2][pr + 1]);
                }
        }
    }
}

// ---------------------------------------------------------------------------
// Kernel: Vc = g_vh @ g_wh   (BN=128, 256 threads, 2 CTAs/SM)
// ---------------------------------------------------------------------------
#define VC_SMEM (NSTG * (A_BYTES + BK * 128 * 2))    // 73728

__global__ __launch_bounds__(256, 2) void vc_gemm_kernel()
{
    const int tid = threadIdx.x;
    const int wid = tid >> 5, lane = tid & 31;
    const int gid = lane >> 2, tig = lane & 3;
    const int wm = (wid >> 2) * 64;
    const int wn = (wid & 3) * 32;

    const int e0 = blockIdx.x * 128;
    const int row0 = blockIdx.y * BM;

    float acc[4][4][4];
#pragma unroll
    for (int a = 0; a < 4; a++)
#pragma unroll
        for (int b = 0; b < 4; b++)
#pragma unroll
            for (int c = 0; c < 4; c++) acc[a][b][c] = 0.f;

    gemm_core_h<128, 256>(g_vh + (long)row0 * EMB, EMB, g_wh + e0, acc, EMB / BK);

#pragma unroll
    for (int mt = 0; mt < 4; mt++) {
        int r0a = row0 + wm + mt * 16 + gid;
#pragma unroll
        for (int nt = 0; nt < 4; nt++) {
            int col = e0 + wn + nt * 8 + 2 * tig;
            __half2 h0 = __floats2half2_rn(acc[mt][nt][0], acc[mt][nt][1]);
            __half2 h1 = __floats2half2_rn(acc[mt][nt][2], acc[mt][nt][3]);
            *(__half2*)(g_vch + (long)r0a * EMB + col) = h0;
            *(__half2*)(g_vch + (long)(r0a + 8) * EMB + col) = h1;
        }
    }
}

// ---------------------------------------------------------------------------
// Kernel: out = diag(invcnt) * (g_afh @ g_vch) + bo
// BN=256, 512 threads (16 warps, 2m x 8n), 1 CTA/SM, grid (4,32)=128 balanced.
// ---------------------------------------------------------------------------
#define MS_SMEM (NSTG * (A_BYTES + BK * 256 * 2))    // 106496

__global__ __launch_bounds__(512, 1) void masked_gemm_kernel(
    const float* __restrict__ bo, float* __restrict__ Y)
{
    const int tid = threadIdx.x;
    const int wid = tid >> 5, lane = tid & 31;
    const int gid = lane >> 2, tig = lane & 3;
    const int wm = (wid >> 3) * 64;
    const int wn = (wid & 7) * 32;

    const int e0 = blockIdx.x * 256;
    const int row0 = blockIdx.y * BM;
    const int n = row0 / SEQ;

    float acc[4][4][4];
#pragma unroll
    for (int a = 0; a < 4; a++)
#pragma unroll
        for (int b = 0; b < 4; b++)
#pragma unroll
            for (int c = 0; c < 4; c++) acc[a][b][c] = 0.f;

    gemm_core_h<256, 512>(g_afh + (long)row0 * SEQ, SEQ,
                          g_vch + (long)n * SEQ * EMB + e0, acc, SEQ / BK);

#pragma unroll
    for (int mt = 0; mt < 4; mt++) {
        int r0a = row0 + wm + mt * 16 + gid;
        float s0 = g_invcnt[r0a];
        float s1 = g_invcnt[r0a + 8];
#pragma unroll
        for (int nt = 0; nt < 4; nt++) {
            int col = e0 + wn + nt * 8 + 2 * tig;
            float b0v = bo[col], b1v = bo[col + 1];
            float2 v0 = make_float2(acc[mt][nt][0] * s0 + b0v, acc[mt][nt][1] * s0 + b1v);
            float2 v1 = make_float2(acc[mt][nt][2] * s1 + b0v, acc[mt][nt][3] * s1 + b1v);
            *(float2*)(Y + (long)r0a * EMB + col) = v0;
            *(float2*)(Y + (long)(r0a + 8) * EMB + col) = v1;
        }
    }
}

// ---------------------------------------------------------------------------
extern "C" void kernel_launch(void* const* d_in, const int* in_sizes, int n_in,
                              void* d_out, int out_size)
{
    const float* value = (const float*)d_in[0];
    // key/query/Wk/Wq unused: masked_fill(+1e20) before softmax forces all
    // unmasked scores to underflow; output is the masked average of projected V.
    const int*   mask  = (const int*)d_in[3];
    const float* Wv    = (const float*)d_in[4];
    const float* Wo    = (const float*)d_in[7];
    const float* bo    = (const float*)d_in[8];
    float* out = (float*)d_out;

    cudaFuncSetAttribute(vc_gemm_kernel,
                         cudaFuncAttributeMaxDynamicSharedMemorySize, VC_SMEM);
    cudaFuncSetAttribute(masked_gemm_kernel,
                         cudaFuncAttributeMaxDynamicSharedMemorySize, MS_SMEM);

    prep_kernel<<<PREP_GRID, 256>>>(value, mask, Wv, Wo);
    {
        dim3 grid(EMB / 128, NROWS / BM);           // (8, 32) = 256
        vc_gemm_kernel<<<grid, 256, VC_SMEM>>>();
    }
    {
        dim3 grid(EMB / 256, NROWS / BM);           // (4, 32) = 128, 1/SM balanced
        masked_gemm_kernel<<<grid, 512, MS_SMEM>>>(bo, out);
    }
}